// round 3
// baseline (speedup 1.0000x reference)
#include <cuda_runtime.h>

#define NATOMS 11776
#define NB     368
#define NTOK   512
#define NL     3
#define MB     16
#define SMS    20

// ---- scratch ----
__device__ float g_sln[NATOMS*128];
__device__ float g_a  [NATOMS*128];
__device__ float g_qkv[NATOMS*384];   // later reused for atom_out
__device__ float g_o  [NATOMS*128];
__device__ float g_ph [NATOMS*16];
__device__ float g_pw [NB*128*16];
__device__ float g_pb [NB*4*32*128];
__device__ float g_tok[NTOK*384];
__device__ float g_u  [NTOK*256];

// ---- transposed weights (k-major) ----
__device__ float gT_cond[128*128];
__device__ float gT_ph[128*16];
__device__ float gT_pw[128*16];
__device__ float gT_sln[NL*128*256];
__device__ float gT_qkv[NL*128*384];
__device__ float gT_out[NL*128*128];
__device__ float gT_ada[NL*128*256];
__device__ float gT_ta [NL*128*512];
__device__ float gT_tb [NL*256*128];
__device__ float gT_gate[NL*128*128];
__device__ float gT_tok[128*384];
__device__ float gT_trunk[384*384];
__device__ float gT_struc[384*384];
__device__ float gT_pairin[32*128];
__device__ float gT_outer[384*256];

__device__ __forceinline__ float sigf(float x){ return 1.0f/(1.0f+__expf(-x)); }

#define LD16(x0,x1,x2,x3,base) { const float4* _p=(const float4*)(base); \
  x0=_p[0]; x1=_p[1]; x2=_p[2]; x3=_p[3]; }
#define FMA16(acc,wv_,x0,x1,x2,x3) { \
  acc[0]+=x0.x*(wv_);  acc[1]+=x0.y*(wv_);  acc[2]+=x0.z*(wv_);  acc[3]+=x0.w*(wv_); \
  acc[4]+=x1.x*(wv_);  acc[5]+=x1.y*(wv_);  acc[6]+=x1.z*(wv_);  acc[7]+=x1.w*(wv_); \
  acc[8]+=x2.x*(wv_);  acc[9]+=x2.y*(wv_);  acc[10]+=x2.z*(wv_); acc[11]+=x2.w*(wv_); \
  acc[12]+=x3.x*(wv_); acc[13]+=x3.y*(wv_); acc[14]+=x3.z*(wv_); acc[15]+=x3.w*(wv_); }
#define ZERO16(a) { _Pragma("unroll") for(int _m=0;_m<16;_m++) a[_m]=0.f; }

// per-atom mean/rstd over 128 dims; 128 threads hold v[m]=dim tid of atom m.
// stage needs >= 2256 floats; starts and ends with __syncthreads.
__device__ __forceinline__ void rowstats128(const float v[16], float* stage,
                                            float mu[16], float rs[16])
{
    const int tid = threadIdx.x;
    const int row = tid>>3, seg = tid&7;
    for (int pass=0; pass<2; pass++){
        __syncthreads();
        #pragma unroll
        for (int m=0;m<16;m++){
            float x = (pass==0)? v[m] : (v[m]-mu[m]);
            stage[m*132+tid] = (pass==0)? x : x*x;
        }
        __syncthreads();
        { float s=0;
          #pragma unroll
          for (int u=0;u<16;u++) s+=stage[row*132+seg*16+u];
          stage[2112+tid]=s; }
        __syncthreads();
        if (tid<16){ float t2=0;
          #pragma unroll
          for (int u=0;u<8;u++) t2+=stage[2112+tid*8+u];
          stage[2240+tid]=t2*(1.0f/128.0f); }
        __syncthreads();
        if (pass==0){
            #pragma unroll
            for (int m=0;m<16;m++) mu[m]=stage[2240+m];
        } else {
            #pragma unroll
            for (int m=0;m<16;m++) rs[m]=rsqrtf(stage[2240+m]+1e-5f);
        }
    }
    __syncthreads();
}

// dst[l][c*R+r] = src[l][r*C+c]
__global__ void k_transpose(float* dst, const float* src, int R, int C)
{
    int idx = blockIdx.x*blockDim.x + threadIdx.x;
    int l = blockIdx.y;
    if (idx < R*C){
        int r = idx / C, c = idx % C;
        dst[(size_t)l*R*C + (size_t)c*R + r] = src[(size_t)l*R*C + (size_t)r*C + c];
    }
}

// K1: c = af@Wcond^T ; a=c ; s_ln=LN(c)
__global__ void __launch_bounds__(128) k_cond(const float* __restrict__ af)
{
    __shared__ __align__(16) float sA[128*SMS];
    int j = threadIdx.x; int a0 = blockIdx.x*MB;
    for (int idx=j; idx<128*MB; idx+=128){
        int m=idx>>7, k=idx&127;
        sA[k*SMS+m] = af[(size_t)(a0+m)*128 + k];
    }
    __syncthreads();
    float acc[16]; ZERO16(acc);
    #pragma unroll 2
    for (int k=0;k<128;k++){
        float wv = gT_cond[k*128+j];
        float4 x0,x1,x2,x3; LD16(x0,x1,x2,x3,&sA[k*SMS]);
        FMA16(acc,wv,x0,x1,x2,x3);
    }
    #pragma unroll
    for (int m=0;m<16;m++) g_a[(size_t)(a0+m)*128+j]=acc[m];
    float mu[16], rs[16];
    rowstats128(acc, sA, mu, rs);
    #pragma unroll
    for (int m=0;m<16;m++) g_sln[(size_t)(a0+m)*128+j]=(acc[m]-mu[m])*rs[m];
}

// K2a: ph = relu(s_ln) @ W_ph^T
__global__ void __launch_bounds__(256) k_ph()
{
    __shared__ float xs[16*132];
    int tid=threadIdx.x; int r0=blockIdx.x*16;
    for (int idx=tid; idx<16*128; idx+=256){
        int r=idx>>7,k=idx&127;
        xs[r*132+k]=fmaxf(g_sln[(size_t)(r0+r)*128+k],0.f);
    }
    __syncthreads();
    int o=tid&15, r=tid>>4;
    float acc=0;
    #pragma unroll 4
    for (int k=0;k<128;k++) acc += xs[r*132+k]*gT_ph[k*16+o];
    g_ph[(size_t)(r0+r)*16+o]=acc;
}

// K2b: pw = relu(s_ln[clamp(window)]) @ W_pw^T
__global__ void __launch_bounds__(256) k_pw()
{
    __shared__ float xs[16*132];
    int tid=threadIdx.x; int r0=blockIdx.x*16;
    for (int idx=tid; idx<16*128; idx+=256){
        int r=idx>>7,k=idx&127;
        int row=r0+r; int nb=row>>7, kk=row&127;
        int atom=nb*32+kk-48; atom=max(0,min(atom,NATOMS-1));
        xs[r*132+k]=fmaxf(g_sln[(size_t)atom*128+k],0.f);
    }
    __syncthreads();
    int o=tid&15, r=tid>>4;
    float acc=0;
    #pragma unroll 4
    for (int k=0;k<128;k++) acc += xs[r*132+k]*gT_pw[k*16+o];
    g_pw[(size_t)(r0+r)*16+o]=acc;
}

// K3: pair bias (p + MLP + LN + head proj + mask fold)
__global__ void __launch_bounds__(128) k_pb(const float* __restrict__ W1g,
                                            const float* __restrict__ W2g,
                                            const float* __restrict__ lnw,
                                            const float* __restrict__ lnb,
                                            const float* __restrict__ pbw)
{
    __shared__ float W1[256], W2[256], PBW[64], LW[16], LB[16], PH[16];
    int tid=threadIdx.x;
    int blk=blockIdx.x; int nb=blk>>5, q=blk&31;
    for (int idx=tid; idx<256; idx+=128){ W1[idx]=W1g[idx]; W2[idx]=W2g[idx]; }
    if (tid<64) PBW[tid]=pbw[tid];
    if (tid<16){ LW[tid]=lnw[tid]; LB[tid]=lnb[tid];
                 PH[tid]=g_ph[(size_t)(nb*32+q)*16+tid]; }
    __syncthreads();

    float p[16];
    { const float4* pwp=(const float4*)&g_pw[(size_t)(nb*128+tid)*16];
      float4 a=pwp[0],b=pwp[1],c=pwp[2],d=pwp[3];
      p[0]=a.x;p[1]=a.y;p[2]=a.z;p[3]=a.w; p[4]=b.x;p[5]=b.y;p[6]=b.z;p[7]=b.w;
      p[8]=c.x;p[9]=c.y;p[10]=c.z;p[11]=c.w; p[12]=d.x;p[13]=d.y;p[14]=d.z;p[15]=d.w; }
    #pragma unroll
    for (int i=0;i<16;i++) p[i]+=PH[i];

    float t[16], u[16];
    #pragma unroll
    for (int i=0;i<16;i++) t[i]=fmaxf(p[i],0.f);
    #pragma unroll
    for (int o=0;o<16;o++){
        float s=0;
        #pragma unroll
        for (int i=0;i<16;i++) s+=t[i]*W1[o*16+i];
        u[o]=fmaxf(s,0.f);
    }
    #pragma unroll
    for (int o=0;o<16;o++){
        float s=0;
        #pragma unroll
        for (int i=0;i<16;i++) s+=u[i]*W2[o*16+i];
        p[o]+=s;
    }
    float mu=0;
    #pragma unroll
    for (int i=0;i<16;i++) mu+=p[i];
    mu*=(1.0f/16.0f);
    float var=0;
    #pragma unroll
    for (int i=0;i<16;i++){ float d=p[i]-mu; var+=d*d; }
    float rsd=rsqrtf(var*(1.0f/16.0f)+1e-5f);
    float y[16];
    #pragma unroll
    for (int i=0;i<16;i++) y[i]=(p[i]-mu)*rsd*LW[i]+LB[i];

    int win = nb*32 + tid - 48;
    float neg = (win>=0 && win<NATOMS) ? 0.f : -1.0e9f;
    #pragma unroll
    for (int h=0;h<4;h++){
        float s=0;
        #pragma unroll
        for (int i=0;i<16;i++) s+=y[i]*PBW[h*16+i];
        g_pb[(size_t)((nb*4+h)*32+q)*128+tid]=s+neg;
    }
}

// K4: per-layer stage A: x = sig(gb_lo)*LN(a)+gb_hi ; qkv = x@qkv_w^T (+q_bias)
__global__ void __launch_bounds__(128) k_stageA(const float* __restrict__ qbias, int l)
{
    __shared__ __align__(16) float sB[128*SMS];
    __shared__ __align__(16) float sA[128*SMS];
    int j=threadIdx.x; int a0=blockIdx.x*MB;
    for (int idx=j; idx<128*MB; idx+=128){
        int m=idx>>7,k=idx&127;
        sB[k*SMS+m]=g_sln[(size_t)(a0+m)*128+k];
    }
    float av[16];
    #pragma unroll
    for (int m=0;m<16;m++) av[m]=g_a[(size_t)(a0+m)*128+j];
    __syncthreads();

    float mu[16],rs[16];
    rowstats128(av, sA, mu, rs);

    const float* Wt = gT_sln + (size_t)l*128*256;
    float acc0[16],acc1[16]; ZERO16(acc0); ZERO16(acc1);
    #pragma unroll 2
    for (int k=0;k<128;k++){
        float w0=Wt[k*256+j], w1=Wt[k*256+128+j];
        float4 x0,x1,x2,x3; LD16(x0,x1,x2,x3,&sB[k*SMS]);
        FMA16(acc0,w0,x0,x1,x2,x3);
        FMA16(acc1,w1,x0,x1,x2,x3);
    }
    #pragma unroll
    for (int m=0;m<16;m++) sA[j*SMS+m]=sigf(acc0[m])*((av[m]-mu[m])*rs[m])+acc1[m];
    __syncthreads();

    const float* Wq = gT_qkv + (size_t)l*128*384;
    float qb = qbias[l*128+j];
    float aq[16],ak[16],avv[16]; ZERO16(aq); ZERO16(ak); ZERO16(avv);
    #pragma unroll 2
    for (int k=0;k<128;k++){
        float w0=Wq[k*384+j], w1=Wq[k*384+128+j], w2=Wq[k*384+256+j];
        float4 x0,x1,x2,x3; LD16(x0,x1,x2,x3,&sA[k*SMS]);
        FMA16(aq,w0,x0,x1,x2,x3);
        FMA16(ak,w1,x0,x1,x2,x3);
        FMA16(avv,w2,x0,x1,x2,x3);
    }
    #pragma unroll
    for (int m=0;m<16;m++){
        size_t b=(size_t)(a0+m)*384;
        g_qkv[b+j]=aq[m]+qb;
        g_qkv[b+128+j]=ak[m];
        g_qkv[b+256+j]=avv[m];
    }
}

// K5: windowed attention per (nb, head)
__global__ void __launch_bounds__(128) k_attn()
{
    extern __shared__ float sm[];
    float* kb = sm;            // 128*33
    float* vb = kb + 128*33;   // 128*33
    float* qb = vb + 128*33;   // 32*32
    float* sc = qb + 32*32;    // 32*129
    int blk=blockIdx.x; int nb=blk>>2, h=blk&3;
    int tid=threadIdx.x;

    for (int idx=tid; idx<128*32; idx+=128){
        int kk=idx>>5, d=idx&31;
        int atom=nb*32+kk-48; atom=max(0,min(atom,NATOMS-1));
        kb[kk*33+d]=g_qkv[(size_t)atom*384+128+h*32+d];
        vb[kk*33+d]=g_qkv[(size_t)atom*384+256+h*32+d];
    }
    for (int idx=tid; idx<32*32; idx+=128){
        int qq=idx>>5,d=idx&31;
        qb[qq*32+d]=g_qkv[(size_t)(nb*32+qq)*384 + h*32 + d];
    }
    __syncthreads();

    const float scale = 0.1767766952966369f;
    const float* pbp = &g_pb[(size_t)((nb*4+h)*32)*128];
    int kk=tid;
    #pragma unroll 1
    for (int qq=0;qq<32;qq++){
        float acc=0;
        #pragma unroll
        for (int d=0;d<32;d++) acc += qb[qq*32+d]*kb[kk*33+d];
        sc[qq*129+kk]=acc*scale + pbp[(size_t)qq*128+kk];
    }
    __syncthreads();

    int qq2=tid>>2, sub=tid&3;
    float mx=-1e30f;
    #pragma unroll 4
    for (int i=0;i<32;i++) mx=fmaxf(mx, sc[qq2*129+sub+4*i]);
    mx=fmaxf(mx,__shfl_xor_sync(0xffffffffu,mx,1));
    mx=fmaxf(mx,__shfl_xor_sync(0xffffffffu,mx,2));
    float s=0;
    #pragma unroll 4
    for (int i=0;i<32;i++){
        int id=qq2*129+sub+4*i;
        float e=__expf(sc[id]-mx); sc[id]=e; s+=e;
    }
    s+=__shfl_xor_sync(0xffffffffu,s,1);
    s+=__shfl_xor_sync(0xffffffffu,s,2);
    float inv=1.0f/s;
    #pragma unroll 4
    for (int i=0;i<32;i++) sc[qq2*129+sub+4*i]*=inv;
    __syncthreads();

    #pragma unroll 1
    for (int i=0;i<8;i++){
        int id=tid+i*128; int qq=id>>5, d=id&31;
        float acc=0;
        #pragma unroll 4
        for (int k=0;k<128;k++) acc += sc[qq*129+k]*vb[k*33+d];
        g_o[(size_t)(nb*32+qq)*128 + h*32 + d]=acc;
    }
}

// K7: per-layer stage C: out proj + ada + transition + gate
__global__ void __launch_bounds__(128) k_stageC(const float* __restrict__ outb,
                                                const float* __restrict__ gateb, int l)
{
    __shared__ __align__(16) float sA[128*SMS];
    __shared__ __align__(16) float sB[128*SMS];
    __shared__ __align__(16) float sC[256*SMS];
    int j=threadIdx.x; int a0=blockIdx.x*MB;
    for (int idx=j; idx<128*MB; idx+=128){
        int m=idx>>7,k=idx&127;
        sA[k*SMS+m]=g_o  [(size_t)(a0+m)*128+k];
        sB[k*SMS+m]=g_sln[(size_t)(a0+m)*128+k];
    }
    float av[16];
    #pragma unroll
    for (int m=0;m<16;m++) av[m]=g_a[(size_t)(a0+m)*128+j];
    __syncthreads();

    float anew[16], gacc[16]; ZERO16(gacc);
    {
        const float* Wo = gT_out  + (size_t)l*128*128;
        const float* Wg = gT_gate + (size_t)l*128*128;
        float acc[16]; ZERO16(acc);
        #pragma unroll 2
        for (int k=0;k<128;k++){
            float wo=Wo[k*128+j], wg=Wg[k*128+j];
            float4 x0,x1,x2,x3; LD16(x0,x1,x2,x3,&sA[k*SMS]);
            FMA16(acc,wo,x0,x1,x2,x3);
            float4 y0,y1,y2,y3; LD16(y0,y1,y2,y3,&sB[k*SMS]);
            FMA16(gacc,wg,y0,y1,y2,y3);
        }
        float ob=outb[l*128+j];
        #pragma unroll
        for (int m=0;m<16;m++) anew[m]=av[m]+acc[m]+ob;
    }

    float mu[16],rs[16];
    rowstats128(anew, sC, mu, rs);

    {
        const float* Wd = gT_ada + (size_t)l*128*256;
        float acc0[16],acc1[16]; ZERO16(acc0); ZERO16(acc1);
        #pragma unroll 2
        for (int k=0;k<128;k++){
            float w0=Wd[k*256+j], w1=Wd[k*256+128+j];
            float4 x0,x1,x2,x3; LD16(x0,x1,x2,x3,&sB[k*SMS]);
            FMA16(acc0,w0,x0,x1,x2,x3);
            FMA16(acc1,w1,x0,x1,x2,x3);
        }
        #pragma unroll
        for (int m=0;m<16;m++)
            sA[j*SMS+m]=sigf(acc0[m])*((anew[m]-mu[m])*rs[m])+acc1[m];
    }
    __syncthreads();

    {
        const float* Wt = gT_ta + (size_t)l*128*512;
        for (int s=0;s<2;s++){
            float accL[16],accH[16]; ZERO16(accL); ZERO16(accH);
            #pragma unroll 2
            for (int k=0;k<128;k++){
                float wl=Wt[k*512 + s*128 + j];
                float wh=Wt[k*512 + s*128 + 256 + j];
                float4 x0,x1,x2,x3; LD16(x0,x1,x2,x3,&sA[k*SMS]);
                FMA16(accL,wl,x0,x1,x2,x3);
                FMA16(accH,wh,x0,x1,x2,x3);
            }
            #pragma unroll
            for (int m=0;m<16;m++){
                float a_=accL[m];
                sC[(s*128+j)*SMS+m]=a_*sigf(a_)*accH[m];
            }
        }
    }
    __syncthreads();

    float hv[16]; ZERO16(hv);
    {
        const float* Wb = gT_tb + (size_t)l*256*128;
        #pragma unroll 2
        for (int k=0;k<256;k++){
            float wv=Wb[k*128+j];
            float4 x0,x1,x2,x3; LD16(x0,x1,x2,x3,&sC[k*SMS]);
            FMA16(hv,wv,x0,x1,x2,x3);
        }
    }
    float gb_=gateb[l*128+j];
    #pragma unroll
    for (int m=0;m<16;m++)
        g_a[(size_t)(a0+m)*128+j]=anew[m]+sigf(gacc[m]+gb_)*hv[m];
}

// K8: atom_out = relu(a @ W_tok^T) -> g_qkv (reuse, 384 wide)
__global__ void __launch_bounds__(128) k_tokproj()
{
    __shared__ __align__(16) float sA[128*SMS];
    int j=threadIdx.x; int a0=blockIdx.x*MB;
    for (int idx=j; idx<128*MB; idx+=128){
        int m=idx>>7,k=idx&127;
        sA[k*SMS+m]=g_a[(size_t)(a0+m)*128+k];
    }
    __syncthreads();
    float a0v[16],a1v[16],a2v[16]; ZERO16(a0v); ZERO16(a1v); ZERO16(a2v);
    #pragma unroll 2
    for (int k=0;k<128;k++){
        float w0=gT_tok[k*384+j], w1=gT_tok[k*384+128+j], w2=gT_tok[k*384+256+j];
        float4 x0,x1,x2,x3; LD16(x0,x1,x2,x3,&sA[k*SMS]);
        FMA16(a0v,w0,x0,x1,x2,x3);
        FMA16(a1v,w1,x0,x1,x2,x3);
        FMA16(a2v,w2,x0,x1,x2,x3);
    }
    #pragma unroll
    for (int m=0;m<16;m++){
        size_t b=(size_t)(a0+m)*384;
        g_qkv[b+j]=fmaxf(a0v[m],0.f);
        g_qkv[b+128+j]=fmaxf(a1v[m],0.f);
        g_qkv[b+256+j]=fmaxf(a2v[m],0.f);
    }
}

// K9: deterministic segment mean over sorted atom_to_token
__global__ void __launch_bounds__(128) k_tokmean(const int* __restrict__ a2t)
{
    __shared__ int slo,shi;
    int t=blockIdx.x;
    if (threadIdx.x==0){
        int lo=0,hi=NATOMS;
        while(lo<hi){int mid=(lo+hi)>>1; if(a2t[mid]<t) lo=mid+1; else hi=mid;}
        slo=lo; int lo2=lo; hi=NATOMS;
        while(lo2<hi){int mid=(lo2+hi)>>1; if(a2t[mid]<t+1) lo2=mid+1; else hi=mid;}
        shi=lo2;
    }
    __syncthreads();
    int lo=slo,hi=shi;
    float inv=1.0f/fmaxf((float)(hi-lo),1.0f);
    #pragma unroll
    for (int s=0;s<3;s++){
        int d=s*128+threadIdx.x;
        float sum=0;
        for (int a=lo;a<hi;a++) sum+=g_qkv[(size_t)a*384+d];
        g_tok[(size_t)t*384+d]=sum*inv;
    }
}

// K10: s_trunk, s_struct -> d_out ; u -> g_u
__global__ void __launch_bounds__(128) k_trunkstruct(float* __restrict__ out)
{
    __shared__ __align__(16) float sT[384*SMS];
    int j=threadIdx.x; int t0=blockIdx.x*MB;
    for (int idx=j; idx<384*MB; idx+=128){
        int m=idx/384, k=idx%384;
        sT[k*SMS+m]=g_tok[(size_t)(t0+m)*384+k];
    }
    __syncthreads();
    {
        float c0[16],c1[16],c2[16]; ZERO16(c0); ZERO16(c1); ZERO16(c2);
        #pragma unroll 2
        for (int k=0;k<384;k++){
            float w0=gT_trunk[k*384+j], w1=gT_trunk[k*384+128+j], w2=gT_trunk[k*384+256+j];
            float4 x0,x1,x2,x3; LD16(x0,x1,x2,x3,&sT[k*SMS]);
            FMA16(c0,w0,x0,x1,x2,x3); FMA16(c1,w1,x0,x1,x2,x3); FMA16(c2,w2,x0,x1,x2,x3);
        }
        #pragma unroll
        for (int m=0;m<16;m++){
            size_t b=(size_t)(t0+m)*384;
            out[b+j]=c0[m]; out[b+128+j]=c1[m]; out[b+256+j]=c2[m];
        }
    }
    {
        float* o2 = out + (size_t)NTOK*384;
        float c0[16],c1[16],c2[16]; ZERO16(c0); ZERO16(c1); ZERO16(c2);
        #pragma unroll 2
        for (int k=0;k<384;k++){
            float w0=gT_struc[k*384+j], w1=gT_struc[k*384+128+j], w2=gT_struc[k*384+256+j];
            float4 x0,x1,x2,x3; LD16(x0,x1,x2,x3,&sT[k*SMS]);
            FMA16(c0,w0,x0,x1,x2,x3); FMA16(c1,w1,x0,x1,x2,x3); FMA16(c2,w2,x0,x1,x2,x3);
        }
        #pragma unroll
        for (int m=0;m<16;m++){
            size_t b=(size_t)(t0+m)*384;
            o2[b+j]=c0[m]; o2[b+128+j]=c1[m]; o2[b+256+j]=c2[m];
        }
    }
    {
        float c0[16],c1[16]; ZERO16(c0); ZERO16(c1);
        #pragma unroll 2
        for (int k=0;k<384;k++){
            float w0=gT_outer[k*256+j], w1=gT_outer[k*256+128+j];
            float4 x0,x1,x2,x3; LD16(x0,x1,x2,x3,&sT[k*SMS]);
            FMA16(c0,w0,x0,x1,x2,x3); FMA16(c1,w1,x0,x1,x2,x3);
        }
        #pragma unroll
        for (int m=0;m<16;m++){
            size_t b=(size_t)(t0+m)*256;
            g_u[b+j]=c0[m]; g_u[b+128+j]=c1[m];
        }
    }
}

// K11: pair = tpf@W_pairin^T + u_lo[i] + u_hi[j]
__global__ void __launch_bounds__(256) k_pair(const float* __restrict__ tpf,
                                              float* __restrict__ outp)
{
    __shared__ float Wp[32*128];
    __shared__ float ui[128];
    __shared__ float tj[64];
    int i=blockIdx.x, tid=threadIdx.x;
    for (int idx=tid; idx<32*128; idx+=256) Wp[idx]=gT_pairin[idx];
    if (tid<128) ui[tid]=g_u[(size_t)i*256+tid];
    __syncthreads();
    int c=tid&127, jj=tid>>7;
    for (int j0=0;j0<NTOK;j0+=2){
        if (tid<64) tj[tid]=tpf[((size_t)i*NTOK + j0 + (tid>>5))*32 + (tid&31)];
        __syncthreads();
        int j=j0+jj;
        float acc=ui[c]+g_u[(size_t)j*256+128+c];
        #pragma unroll
        for (int k=0;k<32;k++) acc += tj[jj*32+k]*Wp[k*128+c];
        outp[((size_t)i*NTOK+j)*128+c]=acc;
        __syncthreads();
    }
}

extern "C" void kernel_launch(void* const* d_in, const int* in_sizes, int n_in,
                              void* d_out, int out_size)
{
    const float* af      = (const float*)d_in[0];
    const float* tpf     = (const float*)d_in[1];
    const float* W_cond  = (const float*)d_in[2];
    const float* W_ph    = (const float*)d_in[3];
    const float* W_pw    = (const float*)d_in[4];
    const float* W_mlp1  = (const float*)d_in[5];
    const float* W_mlp2  = (const float*)d_in[6];
    const float* pb_ln_w = (const float*)d_in[7];
    const float* pb_ln_b = (const float*)d_in[8];
    const float* pb_w    = (const float*)d_in[9];
    const float* sln_w   = (const float*)d_in[10];
    const float* qkv_w   = (const float*)d_in[11];
    const float* q_bias  = (const float*)d_in[12];
    const float* out_w   = (const float*)d_in[13];
    const float* out_b   = (const float*)d_in[14];
    const float* ada_w   = (const float*)d_in[15];
    const float* ta_w    = (const float*)d_in[16];
    const float* tb_w    = (const float*)d_in[17];
    const float* gate_w  = (const float*)d_in[18];
    const float* gate_b  = (const float*)d_in[19];
    const float* W_tok   = (const float*)d_in[20];
    const float* W_trunk = (const float*)d_in[21];
    const float* W_struct= (const float*)d_in[22];
    const float* W_pairin= (const float*)d_in[23];
    const float* W_outer = (const float*)d_in[24];
    const int*   a2t     = (const int*)d_in[28];
    float* out = (float*)d_out;

    float *pT_cond,*pT_ph,*pT_pw,*pT_sln,*pT_qkv,*pT_out,*pT_ada,*pT_ta,*pT_tb,
          *pT_gate,*pT_tok,*pT_trunk,*pT_struc,*pT_pairin,*pT_outer;
    cudaGetSymbolAddress((void**)&pT_cond,  gT_cond);
    cudaGetSymbolAddress((void**)&pT_ph,    gT_ph);
    cudaGetSymbolAddress((void**)&pT_pw,    gT_pw);
    cudaGetSymbolAddress((void**)&pT_sln,   gT_sln);
    cudaGetSymbolAddress((void**)&pT_qkv,   gT_qkv);
    cudaGetSymbolAddress((void**)&pT_out,   gT_out);
    cudaGetSymbolAddress((void**)&pT_ada,   gT_ada);
    cudaGetSymbolAddress((void**)&pT_ta,    gT_ta);
    cudaGetSymbolAddress((void**)&pT_tb,    gT_tb);
    cudaGetSymbolAddress((void**)&pT_gate,  gT_gate);
    cudaGetSymbolAddress((void**)&pT_tok,   gT_tok);
    cudaGetSymbolAddress((void**)&pT_trunk, gT_trunk);
    cudaGetSymbolAddress((void**)&pT_struc, gT_struc);
    cudaGetSymbolAddress((void**)&pT_pairin,gT_pairin);
    cudaGetSymbolAddress((void**)&pT_outer, gT_outer);

    #define TP(dst,src,R,C,L) \
        k_transpose<<<dim3(((R)*(C)+255)/256,(L)),256>>>(dst,src,R,C)
    TP(pT_cond,  W_cond,  128,128,1);
    TP(pT_ph,    W_ph,     16,128,1);
    TP(pT_pw,    W_pw,     16,128,1);
    TP(pT_sln,   sln_w,   256,128,3);
    TP(pT_qkv,   qkv_w,   384,128,3);
    TP(pT_out,   out_w,   128,128,3);
    TP(pT_ada,   ada_w,   256,128,3);
    TP(pT_ta,    ta_w,    512,128,3);
    TP(pT_tb,    tb_w,    128,256,3);
    TP(pT_gate,  gate_w,  128,128,3);
    TP(pT_tok,   W_tok,   384,128,1);
    TP(pT_trunk, W_trunk, 384,384,1);
    TP(pT_struc, W_struct,384,384,1);
    TP(pT_pairin,W_pairin,128, 32,1);
    TP(pT_outer, W_outer, 256,384,1);
    #undef TP

    const int NBLK = NATOMS/MB;              // 736
    k_cond<<<NBLK,128>>>(af);
    k_ph  <<<NATOMS/16,256>>>();
    k_pw  <<<NB*128/16,256>>>();
    k_pb  <<<NB*32,128>>>(W_mlp1,W_mlp2,pb_ln_w,pb_ln_b,pb_w);

    cudaFuncSetAttribute(k_attn, cudaFuncAttributeMaxDynamicSharedMemorySize, 56000);
    for (int l=0;l<NL;l++){
        k_stageA<<<NBLK,128>>>(q_bias,l);
        k_attn  <<<NB*4,128,54400>>>();
        k_stageC<<<NBLK,128>>>(out_b,gate_b,l);
    }

    k_tokproj<<<NBLK,128>>>();
    k_tokmean<<<NTOK,128>>>(a2t);
    k_trunkstruct<<<NTOK/MB,128>>>(out);
    k_pair<<<NTOK,256>>>(tpf, out + (size_t)2*NTOK*384);
}

// round 4
// speedup vs baseline: 1.2593x; 1.2593x over previous
#include <cuda_runtime.h>

#define NATOMS 11776
#define NB     368
#define NTOK   512
#define NL     3
#define MB     16
#define SMS    20

// ---- scratch ----
__device__ float g_sln[NATOMS*128];
__device__ float g_a  [NATOMS*128];
__device__ float g_qkv[NATOMS*384];   // later reused for atom_out
__device__ float g_o  [NATOMS*128];
__device__ float g_ph [NATOMS*16];
__device__ float g_pw [NB*128*16];
__device__ float g_pb [NB*4*32*128];
__device__ float g_tok[NTOK*384];
__device__ float g_u  [NTOK*256];

// ---- packed weights: P[(k/4)*OUT + j] = float4{ W[j][k],W[j][k+1],W[j][k+2],W[j][k+3] } ----
__device__ float4 gP_cond [32*128];
__device__ float4 gP_ph   [32*16];
__device__ float4 gP_pw   [32*16];
__device__ float4 gP_sln  [NL*32*256];
__device__ float4 gP_qkv  [NL*32*384];
__device__ float4 gP_out  [NL*32*128];
__device__ float4 gP_ada  [NL*32*256];
__device__ float4 gP_ta   [NL*32*512];
__device__ float4 gP_tb   [NL*64*128];
__device__ float4 gP_gate [NL*32*128];
__device__ float4 gP_tok  [32*384];
__device__ float4 gP_trunk[96*384];
__device__ float4 gP_struc[96*384];
__device__ float4 gP_pairin[8*128];
__device__ float4 gP_outer[96*256];

__device__ __forceinline__ float sigf(float x){ return 1.0f/(1.0f+__expf(-x)); }

#define LD16(x0,x1,x2,x3,base) { const float4* _p=(const float4*)(base); \
  x0=_p[0]; x1=_p[1]; x2=_p[2]; x3=_p[3]; }
#define FMA16(acc,wv_,x0,x1,x2,x3) { \
  acc[0]+=x0.x*(wv_);  acc[1]+=x0.y*(wv_);  acc[2]+=x0.z*(wv_);  acc[3]+=x0.w*(wv_); \
  acc[4]+=x1.x*(wv_);  acc[5]+=x1.y*(wv_);  acc[6]+=x1.z*(wv_);  acc[7]+=x1.w*(wv_); \
  acc[8]+=x2.x*(wv_);  acc[9]+=x2.y*(wv_);  acc[10]+=x2.z*(wv_); acc[11]+=x2.w*(wv_); \
  acc[12]+=x3.x*(wv_); acc[13]+=x3.y*(wv_); acc[14]+=x3.z*(wv_); acc[15]+=x3.w*(wv_); }
#define ZERO16(a) { _Pragma("unroll") for(int _m=0;_m<16;_m++) a[_m]=0.f; }
#define ZERON(a,N) { _Pragma("unroll") for(int _n=0;_n<(N);_n++) ZERO16(a[_n]); }

// Register-blocked GEMV: NC output chunks of 128 (chunk offset COFF float4),
// x tile in smem [k][m] (stride SMS), packed weights.
template<int K4, int NC, int COFF=128>
__device__ __forceinline__ void gemvN(const float4* __restrict__ Wb, int out4,
                                      const float* __restrict__ sX, float (*acc)[16])
{
    #pragma unroll 2
    for (int k4=0;k4<K4;k4++){
        float4 w[NC];
        #pragma unroll
        for (int n=0;n<NC;n++) w[n]=Wb[k4*out4 + n*COFF];
        const float* xb = sX + (k4<<2)*SMS;
        #pragma unroll
        for (int c=0;c<4;c++){
            float4 x0,x1,x2,x3; LD16(x0,x1,x2,x3, xb + c*SMS);
            #pragma unroll
            for (int n=0;n<NC;n++){
                float wc = (c==0)?w[n].x : (c==1)?w[n].y : (c==2)?w[n].z : w[n].w;
                FMA16(acc[n],wc,x0,x1,x2,x3);
            }
        }
    }
}

// per-atom mean/rstd over 128 dims; 128 threads hold v[m]=dim tid of atom m.
// stage needs >= 2256 floats; starts and ends with __syncthreads.
__device__ __forceinline__ void rowstats128(const float v[16], float* stage,
                                            float mu[16], float rs[16])
{
    const int tid = threadIdx.x;
    const int row = tid>>3, seg = tid&7;
    for (int pass=0; pass<2; pass++){
        __syncthreads();
        #pragma unroll
        for (int m=0;m<16;m++){
            float x = (pass==0)? v[m] : (v[m]-mu[m]);
            stage[m*132+tid] = (pass==0)? x : x*x;
        }
        __syncthreads();
        { float s=0;
          #pragma unroll
          for (int u=0;u<16;u++) s+=stage[row*132+seg*16+u];
          stage[2112+tid]=s; }
        __syncthreads();
        if (tid<16){ float t2=0;
          #pragma unroll
          for (int u=0;u<8;u++) t2+=stage[2112+tid*8+u];
          stage[2240+tid]=t2*(1.0f/128.0f); }
        __syncthreads();
        if (pass==0){
            #pragma unroll
            for (int m=0;m<16;m++) mu[m]=stage[2240+m];
        } else {
            #pragma unroll
            for (int m=0;m<16;m++) rs[m]=rsqrtf(stage[2240+m]+1e-5f);
        }
    }
    __syncthreads();
}

// ---- one-shot weight packer (single launch for all 15 weights) ----
struct PackDesc { const float* src; float* dst; int OUT; int K; int L; };
struct PackArgs { PackDesc d[15]; };
__global__ void k_pack(PackArgs pa)
{
    PackDesc pd = pa.d[blockIdx.y];
    int total = pd.L*pd.OUT*pd.K;
    int K4 = pd.K>>2;
    for (int idx = blockIdx.x*256 + threadIdx.x; idx < total; idx += gridDim.x*256){
        int c = idx&3; int t = idx>>2;
        int j = t % pd.OUT; int q = t / pd.OUT;
        int k4 = q % K4;    int l = q / K4;
        pd.dst[idx] = pd.src[((size_t)l*pd.OUT + j)*pd.K + k4*4 + c];
    }
}

// K1: c = af@Wcond^T ; a=c ; s_ln=LN(c)
__global__ void __launch_bounds__(128) k_cond(const float* __restrict__ af)
{
    __shared__ __align__(16) float sA[128*SMS];
    int j = threadIdx.x; int a0 = blockIdx.x*MB;
    for (int idx=j; idx<128*MB; idx+=128){
        int m=idx>>7, k=idx&127;
        sA[k*SMS+m] = af[(size_t)(a0+m)*128 + k];
    }
    __syncthreads();
    float acc[1][16]; ZERON(acc,1);
    gemvN<32,1>(gP_cond + j, 128, sA, acc);
    #pragma unroll
    for (int m=0;m<16;m++) g_a[(size_t)(a0+m)*128+j]=acc[0][m];
    float mu[16], rs[16];
    rowstats128(acc[0], sA, mu, rs);
    #pragma unroll
    for (int m=0;m<16;m++) g_sln[(size_t)(a0+m)*128+j]=(acc[0][m]-mu[m])*rs[m];
}

// K2a: ph = relu(s_ln) @ W_ph^T
__global__ void __launch_bounds__(256) k_ph()
{
    __shared__ float xs[16*132];
    int tid=threadIdx.x; int r0=blockIdx.x*16;
    for (int idx=tid; idx<16*128; idx+=256){
        int r=idx>>7,k=idx&127;
        xs[r*132+k]=fmaxf(g_sln[(size_t)(r0+r)*128+k],0.f);
    }
    __syncthreads();
    int o=tid&15, r=tid>>4;
    float acc=0;
    #pragma unroll 4
    for (int k4=0;k4<32;k4++){
        float4 w = gP_ph[k4*16+o];
        const float* xb=&xs[r*132+k4*4];
        acc += xb[0]*w.x+xb[1]*w.y+xb[2]*w.z+xb[3]*w.w;
    }
    g_ph[(size_t)(r0+r)*16+o]=acc;
}

// K2b: pw = relu(s_ln[clamp(window)]) @ W_pw^T
__global__ void __launch_bounds__(256) k_pw()
{
    __shared__ float xs[16*132];
    int tid=threadIdx.x; int r0=blockIdx.x*16;
    for (int idx=tid; idx<16*128; idx+=256){
        int r=idx>>7,k=idx&127;
        int row=r0+r; int nb=row>>7, kk=row&127;
        int atom=nb*32+kk-48; atom=max(0,min(atom,NATOMS-1));
        xs[r*132+k]=fmaxf(g_sln[(size_t)atom*128+k],0.f);
    }
    __syncthreads();
    int o=tid&15, r=tid>>4;
    float acc=0;
    #pragma unroll 4
    for (int k4=0;k4<32;k4++){
        float4 w = gP_pw[k4*16+o];
        const float* xb=&xs[r*132+k4*4];
        acc += xb[0]*w.x+xb[1]*w.y+xb[2]*w.z+xb[3]*w.w;
    }
    g_pw[(size_t)(r0+r)*16+o]=acc;
}

// K3: pair bias (p + MLP + LN + head proj + mask fold)
__global__ void __launch_bounds__(128) k_pb(const float* __restrict__ W1g,
                                            const float* __restrict__ W2g,
                                            const float* __restrict__ lnw,
                                            const float* __restrict__ lnb,
                                            const float* __restrict__ pbw)
{
    __shared__ float W1[256], W2[256], PBW[64], LW[16], LB[16], PH[16];
    int tid=threadIdx.x;
    int blk=blockIdx.x; int nb=blk>>5, q=blk&31;
    for (int idx=tid; idx<256; idx+=128){ W1[idx]=W1g[idx]; W2[idx]=W2g[idx]; }
    if (tid<64) PBW[tid]=pbw[tid];
    if (tid<16){ LW[tid]=lnw[tid]; LB[tid]=lnb[tid];
                 PH[tid]=g_ph[(size_t)(nb*32+q)*16+tid]; }
    __syncthreads();

    float p[16];
    { const float4* pwp=(const float4*)&g_pw[(size_t)(nb*128+tid)*16];
      float4 a=pwp[0],b=pwp[1],c=pwp[2],d=pwp[3];
      p[0]=a.x;p[1]=a.y;p[2]=a.z;p[3]=a.w; p[4]=b.x;p[5]=b.y;p[6]=b.z;p[7]=b.w;
      p[8]=c.x;p[9]=c.y;p[10]=c.z;p[11]=c.w; p[12]=d.x;p[13]=d.y;p[14]=d.z;p[15]=d.w; }
    #pragma unroll
    for (int i=0;i<16;i++) p[i]+=PH[i];

    float t[16], u[16];
    #pragma unroll
    for (int i=0;i<16;i++) t[i]=fmaxf(p[i],0.f);
    #pragma unroll
    for (int o=0;o<16;o++){
        float s=0;
        #pragma unroll
        for (int i=0;i<16;i++) s+=t[i]*W1[o*16+i];
        u[o]=fmaxf(s,0.f);
    }
    #pragma unroll
    for (int o=0;o<16;o++){
        float s=0;
        #pragma unroll
        for (int i=0;i<16;i++) s+=u[i]*W2[o*16+i];
        p[o]+=s;
    }
    float mu=0;
    #pragma unroll
    for (int i=0;i<16;i++) mu+=p[i];
    mu*=(1.0f/16.0f);
    float var=0;
    #pragma unroll
    for (int i=0;i<16;i++){ float d=p[i]-mu; var+=d*d; }
    float rsd=rsqrtf(var*(1.0f/16.0f)+1e-5f);
    float y[16];
    #pragma unroll
    for (int i=0;i<16;i++) y[i]=(p[i]-mu)*rsd*LW[i]+LB[i];

    int win = nb*32 + tid - 48;
    float neg = (win>=0 && win<NATOMS) ? 0.f : -1.0e9f;
    #pragma unroll
    for (int h=0;h<4;h++){
        float s=0;
        #pragma unroll
        for (int i=0;i<16;i++) s+=y[i]*PBW[h*16+i];
        g_pb[(size_t)((nb*4+h)*32+q)*128+tid]=s+neg;
    }
}

// K4: per-layer stage A: x = sig(gb_lo)*LN(a)+gb_hi ; qkv = x@qkv_w^T (+q_bias)
__global__ void __launch_bounds__(128) k_stageA(const float* __restrict__ qbias, int l)
{
    __shared__ __align__(16) float sB[128*SMS];
    __shared__ __align__(16) float sX[128*SMS];
    int j=threadIdx.x; int a0=blockIdx.x*MB;
    for (int idx=j; idx<128*MB; idx+=128){
        int m=idx>>7,k=idx&127;
        sB[k*SMS+m]=g_sln[(size_t)(a0+m)*128+k];
    }
    float av[16];
    #pragma unroll
    for (int m=0;m<16;m++) av[m]=g_a[(size_t)(a0+m)*128+j];
    __syncthreads();

    float mu[16],rs[16];
    rowstats128(av, sX, mu, rs);

    float acc[2][16]; ZERON(acc,2);
    gemvN<32,2>(gP_sln + (size_t)l*32*256 + j, 256, sB, acc);
    #pragma unroll
    for (int m=0;m<16;m++)
        sX[j*SMS+m]=sigf(acc[0][m])*((av[m]-mu[m])*rs[m])+acc[1][m];
    __syncthreads();

    float q3[3][16]; ZERON(q3,3);
    gemvN<32,3>(gP_qkv + (size_t)l*32*384 + j, 384, sX, q3);
    float qb = qbias[l*128+j];
    #pragma unroll
    for (int m=0;m<16;m++){
        size_t b=(size_t)(a0+m)*384;
        g_qkv[b+j]      =q3[0][m]+qb;
        g_qkv[b+128+j]  =q3[1][m];
        g_qkv[b+256+j]  =q3[2][m];
    }
}

// K5: windowed attention per (nb, head)
__global__ void __launch_bounds__(128) k_attn()
{
    extern __shared__ float sm[];
    float* kb = sm;            // 128*33
    float* vb = kb + 128*33;   // 128*33
    float* qb = vb + 128*33;   // 32*32
    float* sc = qb + 32*32;    // 32*129
    int blk=blockIdx.x; int nb=blk>>2, h=blk&3;
    int tid=threadIdx.x;

    for (int idx=tid; idx<128*32; idx+=128){
        int kk=idx>>5, d=idx&31;
        int atom=nb*32+kk-48; atom=max(0,min(atom,NATOMS-1));
        kb[kk*33+d]=g_qkv[(size_t)atom*384+128+h*32+d];
        vb[kk*33+d]=g_qkv[(size_t)atom*384+256+h*32+d];
    }
    for (int idx=tid; idx<32*32; idx+=128){
        int qq=idx>>5,d=idx&31;
        qb[qq*32+d]=g_qkv[(size_t)(nb*32+qq)*384 + h*32 + d];
    }
    __syncthreads();

    const float scale = 0.1767766952966369f;
    const float* pbp = &g_pb[(size_t)((nb*4+h)*32)*128];
    int kk=tid;
    #pragma unroll 1
    for (int qq=0;qq<32;qq++){
        float acc=0;
        #pragma unroll
        for (int d=0;d<32;d++) acc += qb[qq*32+d]*kb[kk*33+d];
        sc[qq*129+kk]=acc*scale + pbp[(size_t)qq*128+kk];
    }
    __syncthreads();

    int qq2=tid>>2, sub=tid&3;
    float mx=-1e30f;
    #pragma unroll 4
    for (int i=0;i<32;i++) mx=fmaxf(mx, sc[qq2*129+sub+4*i]);
    mx=fmaxf(mx,__shfl_xor_sync(0xffffffffu,mx,1));
    mx=fmaxf(mx,__shfl_xor_sync(0xffffffffu,mx,2));
    float s=0;
    #pragma unroll 4
    for (int i=0;i<32;i++){
        int id=qq2*129+sub+4*i;
        float e=__expf(sc[id]-mx); sc[id]=e; s+=e;
    }
    s+=__shfl_xor_sync(0xffffffffu,s,1);
    s+=__shfl_xor_sync(0xffffffffu,s,2);
    float inv=1.0f/s;
    #pragma unroll 4
    for (int i=0;i<32;i++) sc[qq2*129+sub+4*i]*=inv;
    __syncthreads();

    #pragma unroll 1
    for (int i=0;i<8;i++){
        int id=tid+i*128; int qq=id>>5, d=id&31;
        float acc=0;
        #pragma unroll 4
        for (int k=0;k<128;k++) acc += sc[qq*129+k]*vb[k*33+d];
        g_o[(size_t)(nb*32+qq)*128 + h*32 + d]=acc;
    }
}

// K7: per-layer stage C: out proj + ada + transition + gate
__global__ void __launch_bounds__(128) k_stageC(const float* __restrict__ outb,
                                                const float* __restrict__ gateb, int l)
{
    __shared__ __align__(16) float sA[128*SMS];
    __shared__ __align__(16) float sB[128*SMS];
    __shared__ __align__(16) float sC[256*SMS];
    int j=threadIdx.x; int a0=blockIdx.x*MB;
    for (int idx=j; idx<128*MB; idx+=128){
        int m=idx>>7,k=idx&127;
        sA[k*SMS+m]=g_o  [(size_t)(a0+m)*128+k];
        sB[k*SMS+m]=g_sln[(size_t)(a0+m)*128+k];
    }
    float av[16];
    #pragma unroll
    for (int m=0;m<16;m++) av[m]=g_a[(size_t)(a0+m)*128+j];
    __syncthreads();

    float o1[1][16]; ZERON(o1,1);
    gemvN<32,1>(gP_out + (size_t)l*32*128 + j, 128, sA, o1);
    float gg[1][16]; ZERON(gg,1);
    gemvN<32,1>(gP_gate + (size_t)l*32*128 + j, 128, sB, gg);

    float ob=outb[l*128+j];
    float anew[16];
    #pragma unroll
    for (int m=0;m<16;m++) anew[m]=av[m]+o1[0][m]+ob;

    float mu[16],rs[16];
    rowstats128(anew, sC, mu, rs);

    float ad[2][16]; ZERON(ad,2);
    gemvN<32,2>(gP_ada + (size_t)l*32*256 + j, 256, sB, ad);
    #pragma unroll
    for (int m=0;m<16;m++)
        sA[j*SMS+m]=sigf(ad[0][m])*((anew[m]-mu[m])*rs[m])+ad[1][m];
    __syncthreads();

    #pragma unroll 1
    for (int s=0;s<2;s++){
        float tp[2][16]; ZERON(tp,2);
        gemvN<32,2,256>(gP_ta + (size_t)l*32*512 + s*128 + j, 512, sA, tp);
        #pragma unroll
        for (int m=0;m<16;m++){
            float a_=tp[0][m];
            sC[(s*128+j)*SMS+m]=a_*sigf(a_)*tp[1][m];
        }
    }
    __syncthreads();

    float hv[1][16]; ZERON(hv,1);
    gemvN<64,1>(gP_tb + (size_t)l*64*128 + j, 128, sC, hv);

    float gb_=gateb[l*128+j];
    #pragma unroll
    for (int m=0;m<16;m++)
        g_a[(size_t)(a0+m)*128+j]=anew[m]+sigf(gg[0][m]+gb_)*hv[0][m];
}

// K8: atom_out = relu(a @ W_tok^T) -> g_qkv (reuse, 384 wide)
__global__ void __launch_bounds__(128) k_tokproj()
{
    __shared__ __align__(16) float sA[128*SMS];
    int j=threadIdx.x; int a0=blockIdx.x*MB;
    for (int idx=j; idx<128*MB; idx+=128){
        int m=idx>>7,k=idx&127;
        sA[k*SMS+m]=g_a[(size_t)(a0+m)*128+k];
    }
    __syncthreads();
    float q3[3][16]; ZERON(q3,3);
    gemvN<32,3>(gP_tok + j, 384, sA, q3);
    #pragma unroll
    for (int m=0;m<16;m++){
        size_t b=(size_t)(a0+m)*384;
        g_qkv[b+j]    =fmaxf(q3[0][m],0.f);
        g_qkv[b+128+j]=fmaxf(q3[1][m],0.f);
        g_qkv[b+256+j]=fmaxf(q3[2][m],0.f);
    }
}

// K9: deterministic segment mean over sorted atom_to_token
__global__ void __launch_bounds__(128) k_tokmean(const int* __restrict__ a2t)
{
    __shared__ int slo,shi;
    int t=blockIdx.x;
    if (threadIdx.x==0){
        int lo=0,hi=NATOMS;
        while(lo<hi){int mid=(lo+hi)>>1; if(a2t[mid]<t) lo=mid+1; else hi=mid;}
        slo=lo; int lo2=lo; hi=NATOMS;
        while(lo2<hi){int mid=(lo2+hi)>>1; if(a2t[mid]<t+1) lo2=mid+1; else hi=mid;}
        shi=lo2;
    }
    __syncthreads();
    int lo=slo,hi=shi;
    float inv=1.0f/fmaxf((float)(hi-lo),1.0f);
    #pragma unroll
    for (int s=0;s<3;s++){
        int d=s*128+threadIdx.x;
        float sum=0;
        for (int a=lo;a<hi;a++) sum+=g_qkv[(size_t)a*384+d];
        g_tok[(size_t)t*384+d]=sum*inv;
    }
}

// K10: s_trunk, s_struct -> d_out ; u -> g_u
__global__ void __launch_bounds__(128) k_trunkstruct(float* __restrict__ out)
{
    __shared__ __align__(16) float sT[384*SMS];
    int j=threadIdx.x; int t0=blockIdx.x*MB;
    for (int idx=j; idx<384*MB; idx+=128){
        int m=idx/384, k=idx%384;
        sT[k*SMS+m]=g_tok[(size_t)(t0+m)*384+k];
    }
    __syncthreads();
    {
        float c3[3][16]; ZERON(c3,3);
        gemvN<96,3>(gP_trunk + j, 384, sT, c3);
        #pragma unroll
        for (int m=0;m<16;m++){
            size_t b=(size_t)(t0+m)*384;
            out[b+j]=c3[0][m]; out[b+128+j]=c3[1][m]; out[b+256+j]=c3[2][m];
        }
    }
    {
        float* o2 = out + (size_t)NTOK*384;
        float c3[3][16]; ZERON(c3,3);
        gemvN<96,3>(gP_struc + j, 384, sT, c3);
        #pragma unroll
        for (int m=0;m<16;m++){
            size_t b=(size_t)(t0+m)*384;
            o2[b+j]=c3[0][m]; o2[b+128+j]=c3[1][m]; o2[b+256+j]=c3[2][m];
        }
    }
    {
        float c2[2][16]; ZERON(c2,2);
        gemvN<96,2>(gP_outer + j, 256, sT, c2);
        #pragma unroll
        for (int m=0;m<16;m++){
            size_t b=(size_t)(t0+m)*256;
            g_u[b+j]=c2[0][m]; g_u[b+128+j]=c2[1][m];
        }
    }
}

// K11: pair = tpf@W_pairin^T + u_lo[i] + u_hi[j]
__global__ void __launch_bounds__(256) k_pair(const float* __restrict__ tpf,
                                              float* __restrict__ outp)
{
    __shared__ float Wp[32*128];
    __shared__ float ui[128];
    __shared__ float tj[64];
    int i=blockIdx.x, tid=threadIdx.x;
    // de-pack gP_pairin into Wp[k*128 + c]
    const float* pf = (const float*)gP_pairin;
    for (int idx=tid; idx<4096; idx+=256){
        int r=idx&3; int c=(idx>>2)&127; int k4=idx>>9;
        Wp[(k4*4+r)*128+c]=pf[idx];
    }
    if (tid<128) ui[tid]=g_u[(size_t)i*256+tid];
    __syncthreads();
    int c=tid&127, jj=tid>>7;
    for (int j0=0;j0<NTOK;j0+=2){
        if (tid<64) tj[tid]=tpf[((size_t)i*NTOK + j0 + (tid>>5))*32 + (tid&31)];
        __syncthreads();
        int j=j0+jj;
        float acc=ui[c]+g_u[(size_t)j*256+128+c];
        #pragma unroll
        for (int k=0;k<32;k++) acc += tj[jj*32+k]*Wp[k*128+c];
        outp[((size_t)i*NTOK+j)*128+c]=acc;
        __syncthreads();
    }
}

extern "C" void kernel_launch(void* const* d_in, const int* in_sizes, int n_in,
                              void* d_out, int out_size)
{
    const float* af      = (const float*)d_in[0];
    const float* tpf     = (const float*)d_in[1];
    const float* W_cond  = (const float*)d_in[2];
    const float* W_ph    = (const float*)d_in[3];
    const float* W_pw    = (const float*)d_in[4];
    const float* W_mlp1  = (const float*)d_in[5];
    const float* W_mlp2  = (const float*)d_in[6];
    const float* pb_ln_w = (const float*)d_in[7];
    const float* pb_ln_b = (const float*)d_in[8];
    const float* pb_w    = (const float*)d_in[9];
    const float* sln_w   = (const float*)d_in[10];
    const float* qkv_w   = (const float*)d_in[11];
    const float* q_bias  = (const float*)d_in[12];
    const float* out_w   = (const float*)d_in[13];
    const float* out_b   = (const float*)d_in[14];
    const float* ada_w   = (const float*)d_in[15];
    const float* ta_w    = (const float*)d_in[16];
    const float* tb_w    = (const float*)d_in[17];
    const float* gate_w  = (const float*)d_in[18];
    const float* gate_b  = (const float*)d_in[19];
    const float* W_tok   = (const float*)d_in[20];
    const float* W_trunk = (const float*)d_in[21];
    const float* W_struct= (const float*)d_in[22];
    const float* W_pairin= (const float*)d_in[23];
    const float* W_outer = (const float*)d_in[24];
    const int*   a2t     = (const int*)d_in[28];
    float* out = (float*)d_out;

    PackArgs pa;
    void* p;
    #define SETP(i,sym,srcp,OUTv,Kv,Lv) \
        cudaGetSymbolAddress(&p, sym); \
        pa.d[i] = PackDesc{ srcp, (float*)p, OUTv, Kv, Lv };
    SETP(0,  gP_cond,   W_cond,   128,128,1);
    SETP(1,  gP_ph,     W_ph,      16,128,1);
    SETP(2,  gP_pw,     W_pw,      16,128,1);
    SETP(3,  gP_sln,    sln_w,    256,128,3);
    SETP(4,  gP_qkv,    qkv_w,    384,128,3);
    SETP(5,  gP_out,    out_w,    128,128,3);
    SETP(6,  gP_ada,    ada_w,    256,128,3);
    SETP(7,  gP_ta,     ta_w,     512,128,3);
    SETP(8,  gP_tb,     tb_w,     128,256,3);
    SETP(9,  gP_gate,   gate_w,   128,128,3);
    SETP(10, gP_tok,    W_tok,    384,128,1);
    SETP(11, gP_trunk,  W_trunk,  384,384,1);
    SETP(12, gP_struc,  W_struct, 384,384,1);
    SETP(13, gP_pairin, W_pairin, 128, 32,1);
    SETP(14, gP_outer,  W_outer,  256,384,1);
    #undef SETP
    k_pack<<<dim3(96,15),256>>>(pa);

    const int NBLK = NATOMS/MB;              // 736
    k_cond<<<NBLK,128>>>(af);
    k_ph  <<<NATOMS/16,256>>>();
    k_pw  <<<NB*128/16,256>>>();
    k_pb  <<<NB*32,128>>>(W_mlp1,W_mlp2,pb_ln_w,pb_ln_b,pb_w);

    cudaFuncSetAttribute(k_attn, cudaFuncAttributeMaxDynamicSharedMemorySize, 56000);
    for (int l=0;l<NL;l++){
        k_stageA<<<NBLK,128>>>(q_bias,l);
        k_attn  <<<NB*4,128,54400>>>();
        k_stageC<<<NBLK,128>>>(out_b,gate_b,l);
    }

    k_tokproj<<<NBLK,128>>>();
    k_tokmean<<<NTOK,128>>>(a2t);
    k_trunkstruct<<<NTOK/MB,128>>>(out);
    k_pair<<<NTOK,256>>>(tpf, out + (size_t)2*NTOK*384);
}

// round 5
// speedup vs baseline: 1.3321x; 1.0578x over previous
#include <cuda_runtime.h>

#define NATOMS 11776
#define NB     368
#define NTOK   512
#define NL     3
#define MB     16
#define SMS    20

// ---- scratch ----
__device__ float g_sln[NATOMS*128];
__device__ float g_a  [NATOMS*128];
__device__ float g_qkv[NATOMS*384];   // later reused for atom_out
__device__ float g_o  [NATOMS*128];
__device__ float g_ph [NATOMS*16];
__device__ float g_pw [NB*128*16];
__device__ float g_pb [NB*4*32*128];
__device__ float g_tok[NTOK*384];
__device__ float g_u  [NTOK*256];

// ---- packed weights: P[(k/4)*OUT + j] = float4{ W[j][k..k+3] } ----
__device__ float4 gP_cond [32*128];
__device__ float4 gP_ph   [32*16];
__device__ float4 gP_pw   [32*16];
__device__ float4 gP_sln  [NL*32*256];
__device__ float4 gP_qkv  [NL*32*384];
__device__ float4 gP_out  [NL*32*128];
__device__ float4 gP_ada  [NL*32*256];
__device__ float4 gP_ta   [NL*32*512];
__device__ float4 gP_tb   [NL*64*128];
__device__ float4 gP_gate [NL*32*128];
__device__ float4 gP_tok  [32*384];
__device__ float4 gP_trunk[96*384];
__device__ float4 gP_struc[96*384];
__device__ float4 gP_pairin[8*128];
__device__ float4 gP_outer[96*256];

__device__ __forceinline__ float sigf(float x){ return 1.0f/(1.0f+__expf(-x)); }

#define LD16(x0,x1,x2,x3,base) { const float4* _p=(const float4*)(base); \
  x0=_p[0]; x1=_p[1]; x2=_p[2]; x3=_p[3]; }
#define FMA16(acc,wv_,x0,x1,x2,x3) { \
  acc[0]+=x0.x*(wv_);  acc[1]+=x0.y*(wv_);  acc[2]+=x0.z*(wv_);  acc[3]+=x0.w*(wv_); \
  acc[4]+=x1.x*(wv_);  acc[5]+=x1.y*(wv_);  acc[6]+=x1.z*(wv_);  acc[7]+=x1.w*(wv_); \
  acc[8]+=x2.x*(wv_);  acc[9]+=x2.y*(wv_);  acc[10]+=x2.z*(wv_); acc[11]+=x2.w*(wv_); \
  acc[12]+=x3.x*(wv_); acc[13]+=x3.y*(wv_); acc[14]+=x3.z*(wv_); acc[15]+=x3.w*(wv_); }
#define ZERO16(a) { _Pragma("unroll") for(int _m=0;_m<16;_m++) a[_m]=0.f; }
#define ZERON(a,N) { _Pragma("unroll") for(int _n=0;_n<(N);_n++) ZERO16(a[_n]); }

// Register-blocked GEMV: NC output chunks of 128 (chunk offset COFF float4),
// x tile in smem [k][m] (stride SMS), packed weights.
template<int K4, int NC, int COFF=128>
__device__ __forceinline__ void gemvN(const float4* __restrict__ Wb, int out4,
                                      const float* __restrict__ sX, float (*acc)[16])
{
    #pragma unroll 2
    for (int k4=0;k4<K4;k4++){
        float4 w[NC];
        #pragma unroll
        for (int n=0;n<NC;n++) w[n]=Wb[k4*out4 + n*COFF];
        const float* xb = sX + (k4<<2)*SMS;
        #pragma unroll
        for (int c=0;c<4;c++){
            float4 x0,x1,x2,x3; LD16(x0,x1,x2,x3, xb + c*SMS);
            #pragma unroll
            for (int n=0;n<NC;n++){
                float wc = (c==0)?w[n].x : (c==1)?w[n].y : (c==2)?w[n].z : w[n].w;
                FMA16(acc[n],wc,x0,x1,x2,x3);
            }
        }
    }
}

// per-atom mean/rstd over 128 dims; 128 threads hold v[m]=dim tid of atom m.
__device__ __forceinline__ void rowstats128(const float v[16], float* stage,
                                            float mu[16], float rs[16])
{
    const int tid = threadIdx.x;
    const int row = tid>>3, seg = tid&7;
    for (int pass=0; pass<2; pass++){
        __syncthreads();
        #pragma unroll
        for (int m=0;m<16;m++){
            float x = (pass==0)? v[m] : (v[m]-mu[m]);
            stage[m*132+tid] = (pass==0)? x : x*x;
        }
        __syncthreads();
        { float s=0;
          #pragma unroll
          for (int u=0;u<16;u++) s+=stage[row*132+seg*16+u];
          stage[2112+tid]=s; }
        __syncthreads();
        if (tid<16){ float t2=0;
          #pragma unroll
          for (int u=0;u<8;u++) t2+=stage[2112+tid*8+u];
          stage[2240+tid]=t2*(1.0f/128.0f); }
        __syncthreads();
        if (pass==0){
            #pragma unroll
            for (int m=0;m<16;m++) mu[m]=stage[2240+m];
        } else {
            #pragma unroll
            for (int m=0;m<16;m++) rs[m]=rsqrtf(stage[2240+m]+1e-5f);
        }
    }
    __syncthreads();
}

// ---- one-shot weight packer ----
struct PackDesc { const float* src; float* dst; int OUT; int K; int L; };
struct PackArgs { PackDesc d[15]; };
__global__ void k_pack(PackArgs pa)
{
    PackDesc pd = pa.d[blockIdx.y];
    int total = pd.L*pd.OUT*pd.K;
    int K4 = pd.K>>2;
    for (int idx = blockIdx.x*256 + threadIdx.x; idx < total; idx += gridDim.x*256){
        int c = idx&3; int t = idx>>2;
        int j = t % pd.OUT; int q = t / pd.OUT;
        int k4 = q % K4;    int l = q / K4;
        pd.dst[idx] = pd.src[((size_t)l*pd.OUT + j)*pd.K + k4*4 + c];
    }
}

// K1: c = af@Wcond^T ; a=c ; s_ln=LN(c)
__global__ void __launch_bounds__(128) k_cond(const float* __restrict__ af)
{
    __shared__ __align__(16) float sA[128*SMS];
    int j = threadIdx.x; int a0 = blockIdx.x*MB;
    for (int idx=j; idx<128*MB; idx+=128){
        int m=idx>>7, k=idx&127;
        sA[k*SMS+m] = af[(size_t)(a0+m)*128 + k];
    }
    __syncthreads();
    float acc[1][16]; ZERON(acc,1);
    gemvN<32,1>(gP_cond + j, 128, sA, acc);
    #pragma unroll
    for (int m=0;m<16;m++) g_a[(size_t)(a0+m)*128+j]=acc[0][m];
    float mu[16], rs[16];
    rowstats128(acc[0], sA, mu, rs);
    #pragma unroll
    for (int m=0;m<16;m++) g_sln[(size_t)(a0+m)*128+j]=(acc[0][m]-mu[m])*rs[m];
}

// K2a: ph = relu(s_ln) @ W_ph^T
__global__ void __launch_bounds__(256) k_ph()
{
    __shared__ float xs[16*132];
    int tid=threadIdx.x; int r0=blockIdx.x*16;
    for (int idx=tid; idx<16*128; idx+=256){
        int r=idx>>7,k=idx&127;
        xs[r*132+k]=fmaxf(g_sln[(size_t)(r0+r)*128+k],0.f);
    }
    __syncthreads();
    int o=tid&15, r=tid>>4;
    float acc=0;
    #pragma unroll 4
    for (int k4=0;k4<32;k4++){
        float4 w = gP_ph[k4*16+o];
        const float* xb=&xs[r*132+k4*4];
        acc += xb[0]*w.x+xb[1]*w.y+xb[2]*w.z+xb[3]*w.w;
    }
    g_ph[(size_t)(r0+r)*16+o]=acc;
}

// K2b: pw = relu(s_ln[clamp(window)]) @ W_pw^T
__global__ void __launch_bounds__(256) k_pw()
{
    __shared__ float xs[16*132];
    int tid=threadIdx.x; int r0=blockIdx.x*16;
    for (int idx=tid; idx<16*128; idx+=256){
        int r=idx>>7,k=idx&127;
        int row=r0+r; int nb=row>>7, kk=row&127;
        int atom=nb*32+kk-48; atom=max(0,min(atom,NATOMS-1));
        xs[r*132+k]=fmaxf(g_sln[(size_t)atom*128+k],0.f);
    }
    __syncthreads();
    int o=tid&15, r=tid>>4;
    float acc=0;
    #pragma unroll 4
    for (int k4=0;k4<32;k4++){
        float4 w = gP_pw[k4*16+o];
        const float* xb=&xs[r*132+k4*4];
        acc += xb[0]*w.x+xb[1]*w.y+xb[2]*w.z+xb[3]*w.w;
    }
    g_pw[(size_t)(r0+r)*16+o]=acc;
}

// K3: pair bias (p + MLP + LN + head proj + mask fold)
__global__ void __launch_bounds__(128) k_pb(const float* __restrict__ W1g,
                                            const float* __restrict__ W2g,
                                            const float* __restrict__ lnw,
                                            const float* __restrict__ lnb,
                                            const float* __restrict__ pbw)
{
    __shared__ float W1[256], W2[256], PBW[64], LW[16], LB[16], PH[16];
    int tid=threadIdx.x;
    int blk=blockIdx.x; int nb=blk>>5, q=blk&31;
    for (int idx=tid; idx<256; idx+=128){ W1[idx]=W1g[idx]; W2[idx]=W2g[idx]; }
    if (tid<64) PBW[tid]=pbw[tid];
    if (tid<16){ LW[tid]=lnw[tid]; LB[tid]=lnb[tid];
                 PH[tid]=g_ph[(size_t)(nb*32+q)*16+tid]; }
    __syncthreads();

    float p[16];
    { const float4* pwp=(const float4*)&g_pw[(size_t)(nb*128+tid)*16];
      float4 a=pwp[0],b=pwp[1],c=pwp[2],d=pwp[3];
      p[0]=a.x;p[1]=a.y;p[2]=a.z;p[3]=a.w; p[4]=b.x;p[5]=b.y;p[6]=b.z;p[7]=b.w;
      p[8]=c.x;p[9]=c.y;p[10]=c.z;p[11]=c.w; p[12]=d.x;p[13]=d.y;p[14]=d.z;p[15]=d.w; }
    #pragma unroll
    for (int i=0;i<16;i++) p[i]+=PH[i];

    float t[16], u[16];
    #pragma unroll
    for (int i=0;i<16;i++) t[i]=fmaxf(p[i],0.f);
    #pragma unroll
    for (int o=0;o<16;o++){
        float s=0;
        #pragma unroll
        for (int i=0;i<16;i++) s+=t[i]*W1[o*16+i];
        u[o]=fmaxf(s,0.f);
    }
    #pragma unroll
    for (int o=0;o<16;o++){
        float s=0;
        #pragma unroll
        for (int i=0;i<16;i++) s+=u[i]*W2[o*16+i];
        p[o]+=s;
    }
    float mu=0;
    #pragma unroll
    for (int i=0;i<16;i++) mu+=p[i];
    mu*=(1.0f/16.0f);
    float var=0;
    #pragma unroll
    for (int i=0;i<16;i++){ float d=p[i]-mu; var+=d*d; }
    float rsd=rsqrtf(var*(1.0f/16.0f)+1e-5f);
    float y[16];
    #pragma unroll
    for (int i=0;i<16;i++) y[i]=(p[i]-mu)*rsd*LW[i]+LB[i];

    int win = nb*32 + tid - 48;
    float neg = (win>=0 && win<NATOMS) ? 0.f : -1.0e9f;
    #pragma unroll
    for (int h=0;h<4;h++){
        float s=0;
        #pragma unroll
        for (int i=0;i<16;i++) s+=y[i]*PBW[h*16+i];
        g_pb[(size_t)((nb*4+h)*32+q)*128+tid]=s+neg;
    }
}

// K4: per-layer stage A
__global__ void __launch_bounds__(128) k_stageA(const float* __restrict__ qbias, int l)
{
    __shared__ __align__(16) float sB[128*SMS];
    __shared__ __align__(16) float sX[128*SMS];
    int j=threadIdx.x; int a0=blockIdx.x*MB;
    for (int idx=j; idx<128*MB; idx+=128){
        int m=idx>>7,k=idx&127;
        sB[k*SMS+m]=g_sln[(size_t)(a0+m)*128+k];
    }
    float av[16];
    #pragma unroll
    for (int m=0;m<16;m++) av[m]=g_a[(size_t)(a0+m)*128+j];
    __syncthreads();

    float mu[16],rs[16];
    rowstats128(av, sX, mu, rs);

    float acc[2][16]; ZERON(acc,2);
    gemvN<32,2>(gP_sln + (size_t)l*32*256 + j, 256, sB, acc);
    #pragma unroll
    for (int m=0;m<16;m++)
        sX[j*SMS+m]=sigf(acc[0][m])*((av[m]-mu[m])*rs[m])+acc[1][m];
    __syncthreads();

    float q3[3][16]; ZERON(q3,3);
    gemvN<32,3>(gP_qkv + (size_t)l*32*384 + j, 384, sX, q3);
    float qb = qbias[l*128+j];
    #pragma unroll
    for (int m=0;m<16;m++){
        size_t b=(size_t)(a0+m)*384;
        g_qkv[b+j]      =q3[0][m]+qb;
        g_qkv[b+128+j]  =q3[1][m];
        g_qkv[b+256+j]  =q3[2][m];
    }
}

// K5: windowed attention per (nb, head) — outer-product register-blocked
__global__ void __launch_bounds__(128) k_attn()
{
    extern __shared__ float sm[];
    float* vb  = sm;           // 128*33 = 4224
    float* qT  = vb + 4224;    // 32*36  = 1152
    float* sc  = qT + 1152;    // 4224 (32*129 used; aliased as red in AV epilogue)
    float* scT = sc + 4224;    // 128*36 = 4608
    int blk=blockIdx.x; int nb=blk>>2, h=blk&3;
    int tid=threadIdx.x;

    for (int idx=tid; idx<128*32; idx+=128){
        int kk=idx>>5, d=idx&31;
        int atom=nb*32+kk-48; atom=max(0,min(atom,NATOMS-1));
        vb[kk*33+d]=g_qkv[(size_t)atom*384+256+h*32+d];
    }
    for (int idx=tid; idx<1024; idx+=128){
        int d=idx>>5, qq=idx&31;
        qT[d*36+qq]=g_qkv[(size_t)(nb*32+qq)*384 + h*32 + d];
    }
    // this thread's K row in registers
    float kreg[32];
    {
        int atom=nb*32+tid-48; atom=max(0,min(atom,NATOMS-1));
        const float4* kr=(const float4*)&g_qkv[(size_t)atom*384+128+h*32];
        #pragma unroll
        for (int i=0;i<8;i++){
            float4 v=kr[i];
            kreg[i*4]=v.x; kreg[i*4+1]=v.y; kreg[i*4+2]=v.z; kreg[i*4+3]=v.w;
        }
    }
    __syncthreads();

    // QK: acc[qq] = sum_d qT[d][qq]*kreg[d]
    float acc[32];
    #pragma unroll
    for (int i=0;i<32;i++) acc[i]=0.f;
    #pragma unroll 4
    for (int d=0;d<32;d++){
        float kd=kreg[d];
        const float4* qp=(const float4*)&qT[d*36];
        #pragma unroll
        for (int r=0;r<8;r++){
            float4 q4=qp[r];
            acc[r*4]  +=q4.x*kd;
            acc[r*4+1]+=q4.y*kd;
            acc[r*4+2]+=q4.z*kd;
            acc[r*4+3]+=q4.w*kd;
        }
    }
    const float scale=0.1767766952966369f;
    const float* pbp=&g_pb[(size_t)((nb*4+h)*32)*128];
    #pragma unroll 4
    for (int qq=0;qq<32;qq++)
        sc[qq*129+tid]=acc[qq]*scale + pbp[(size_t)qq*128+tid];
    __syncthreads();

    // softmax per qq over 128 kk
    {
        int qq2=tid>>2, sub=tid&3;
        float mx=-1e30f;
        #pragma unroll 4
        for (int i=0;i<32;i++) mx=fmaxf(mx, sc[qq2*129+sub+4*i]);
        mx=fmaxf(mx,__shfl_xor_sync(0xffffffffu,mx,1));
        mx=fmaxf(mx,__shfl_xor_sync(0xffffffffu,mx,2));
        float s=0;
        #pragma unroll 4
        for (int i=0;i<32;i++){
            int id=qq2*129+sub+4*i;
            float e=__expf(sc[id]-mx); sc[id]=e; s+=e;
        }
        s+=__shfl_xor_sync(0xffffffffu,s,1);
        s+=__shfl_xor_sync(0xffffffffu,s,2);
        float inv=1.0f/s;
        #pragma unroll 4
        for (int i=0;i<32;i++) sc[qq2*129+sub+4*i]*=inv;
    }
    __syncthreads();

    // transpose sc -> scT[k][qq]
    for (int idx=tid; idx<4096; idx+=128){
        int qq=idx&31, kk=idx>>5;
        scT[kk*36+qq]=sc[qq*129+kk];
    }
    __syncthreads();

    // AV: thread = (d, kgroup); acc[qq] += scT[k][qq]*vb[k][d]
    #pragma unroll
    for (int i=0;i<32;i++) acc[i]=0.f;
    int d=tid&31, kg=tid>>5;
    #pragma unroll 4
    for (int ki=0;ki<32;ki++){
        int k=kg*32+ki;
        float v=vb[k*33+d];
        const float4* sp=(const float4*)&scT[k*36];
        #pragma unroll
        for (int r=0;r<8;r++){
            float4 s4=sp[r];
            acc[r*4]  +=s4.x*v;
            acc[r*4+1]+=s4.y*v;
            acc[r*4+2]+=s4.z*v;
            acc[r*4+3]+=s4.w*v;
        }
    }
    float* red = sc;  // alias, 4*1056 = 4224 floats
    #pragma unroll
    for (int qq=0;qq<32;qq++) red[kg*1056+qq*33+d]=acc[qq];
    __syncthreads();
    for (int idx=tid; idx<1024; idx+=128){
        int qq=idx>>5, dd=idx&31;
        float s=red[qq*33+dd]+red[1056+qq*33+dd]+red[2112+qq*33+dd]+red[3168+qq*33+dd];
        g_o[(size_t)(nb*32+qq)*128 + h*32 + dd]=s;
    }
}

// K7: per-layer stage C
__global__ void __launch_bounds__(128) k_stageC(const float* __restrict__ outb,
                                                const float* __restrict__ gateb, int l)
{
    __shared__ __align__(16) float sA[128*SMS];
    __shared__ __align__(16) float sB[128*SMS];
    __shared__ __align__(16) float sC[256*SMS];
    int j=threadIdx.x; int a0=blockIdx.x*MB;
    for (int idx=j; idx<128*MB; idx+=128){
        int m=idx>>7,k=idx&127;
        sA[k*SMS+m]=g_o  [(size_t)(a0+m)*128+k];
        sB[k*SMS+m]=g_sln[(size_t)(a0+m)*128+k];
    }
    float av[16];
    #pragma unroll
    for (int m=0;m<16;m++) av[m]=g_a[(size_t)(a0+m)*128+j];
    __syncthreads();

    float o1[1][16]; ZERON(o1,1);
    gemvN<32,1>(gP_out + (size_t)l*32*128 + j, 128, sA, o1);
    float gg[1][16]; ZERON(gg,1);
    gemvN<32,1>(gP_gate + (size_t)l*32*128 + j, 128, sB, gg);

    float ob=outb[l*128+j];
    float anew[16];
    #pragma unroll
    for (int m=0;m<16;m++) anew[m]=av[m]+o1[0][m]+ob;

    float mu[16],rs[16];
    rowstats128(anew, sC, mu, rs);

    float ad[2][16]; ZERON(ad,2);
    gemvN<32,2>(gP_ada + (size_t)l*32*256 + j, 256, sB, ad);
    #pragma unroll
    for (int m=0;m<16;m++)
        sA[j*SMS+m]=sigf(ad[0][m])*((anew[m]-mu[m])*rs[m])+ad[1][m];
    __syncthreads();

    #pragma unroll 1
    for (int s=0;s<2;s++){
        float tp[2][16]; ZERON(tp,2);
        gemvN<32,2,256>(gP_ta + (size_t)l*32*512 + s*128 + j, 512, sA, tp);
        #pragma unroll
        for (int m=0;m<16;m++){
            float a_=tp[0][m];
            sC[(s*128+j)*SMS+m]=a_*sigf(a_)*tp[1][m];
        }
    }
    __syncthreads();

    float hv[1][16]; ZERON(hv,1);
    gemvN<64,1>(gP_tb + (size_t)l*64*128 + j, 128, sC, hv);

    float gb_=gateb[l*128+j];
    #pragma unroll
    for (int m=0;m<16;m++)
        g_a[(size_t)(a0+m)*128+j]=anew[m]+sigf(gg[0][m]+gb_)*hv[0][m];
}

// K8: atom_out = relu(a @ W_tok^T) -> g_qkv (reuse)
__global__ void __launch_bounds__(128) k_tokproj()
{
    __shared__ __align__(16) float sA[128*SMS];
    int j=threadIdx.x; int a0=blockIdx.x*MB;
    for (int idx=j; idx<128*MB; idx+=128){
        int m=idx>>7,k=idx&127;
        sA[k*SMS+m]=g_a[(size_t)(a0+m)*128+k];
    }
    __syncthreads();
    float q3[3][16]; ZERON(q3,3);
    gemvN<32,3>(gP_tok + j, 384, sA, q3);
    #pragma unroll
    for (int m=0;m<16;m++){
        size_t b=(size_t)(a0+m)*384;
        g_qkv[b+j]    =fmaxf(q3[0][m],0.f);
        g_qkv[b+128+j]=fmaxf(q3[1][m],0.f);
        g_qkv[b+256+j]=fmaxf(q3[2][m],0.f);
    }
}

// K9: deterministic segment mean
__global__ void __launch_bounds__(128) k_tokmean(const int* __restrict__ a2t)
{
    __shared__ int slo,shi;
    int t=blockIdx.x;
    if (threadIdx.x==0){
        int lo=0,hi=NATOMS;
        while(lo<hi){int mid=(lo+hi)>>1; if(a2t[mid]<t) lo=mid+1; else hi=mid;}
        slo=lo; int lo2=lo; hi=NATOMS;
        while(lo2<hi){int mid=(lo2+hi)>>1; if(a2t[mid]<t+1) lo2=mid+1; else hi=mid;}
        shi=lo2;
    }
    __syncthreads();
    int lo=slo,hi=shi;
    float inv=1.0f/fmaxf((float)(hi-lo),1.0f);
    #pragma unroll
    for (int s=0;s<3;s++){
        int d=s*128+threadIdx.x;
        float sum=0;
        for (int a=lo;a<hi;a++) sum+=g_qkv[(size_t)a*384+d];
        g_tok[(size_t)t*384+d]=sum*inv;
    }
}

// K10: s_trunk, s_struct -> d_out ; u -> g_u
__global__ void __launch_bounds__(128) k_trunkstruct(float* __restrict__ out)
{
    __shared__ __align__(16) float sT[384*SMS];
    int j=threadIdx.x; int t0=blockIdx.x*MB;
    for (int idx=j; idx<384*MB; idx+=128){
        int m=idx/384, k=idx%384;
        sT[k*SMS+m]=g_tok[(size_t)(t0+m)*384+k];
    }
    __syncthreads();
    {
        float c3[3][16]; ZERON(c3,3);
        gemvN<96,3>(gP_trunk + j, 384, sT, c3);
        #pragma unroll
        for (int m=0;m<16;m++){
            size_t b=(size_t)(t0+m)*384;
            out[b+j]=c3[0][m]; out[b+128+j]=c3[1][m]; out[b+256+j]=c3[2][m];
        }
    }
    {
        float* o2 = out + (size_t)NTOK*384;
        float c3[3][16]; ZERON(c3,3);
        gemvN<96,3>(gP_struc + j, 384, sT, c3);
        #pragma unroll
        for (int m=0;m<16;m++){
            size_t b=(size_t)(t0+m)*384;
            o2[b+j]=c3[0][m]; o2[b+128+j]=c3[1][m]; o2[b+256+j]=c3[2][m];
        }
    }
    {
        float c2[2][16]; ZERON(c2,2);
        gemvN<96,2>(gP_outer + j, 256, sT, c2);
        #pragma unroll
        for (int m=0;m<16;m++){
            size_t b=(size_t)(t0+m)*256;
            g_u[b+j]=c2[0][m]; g_u[b+128+j]=c2[1][m];
        }
    }
}

// K11: pair = tpf@W_pairin^T + u_lo[i] + u_hi[j] — weights in registers
__global__ void __launch_bounds__(128) k_pair(const float* __restrict__ tpf,
                                              float* __restrict__ outp)
{
    __shared__ __align__(16) float tj[8*32];
    int i=blockIdx.x, c=threadIdx.x;
    float4 w[8];
    #pragma unroll
    for (int k4=0;k4<8;k4++) w[k4]=gP_pairin[k4*128+c];
    float uiv=g_u[(size_t)i*256+c];
    for (int j0=0;j0<NTOK;j0+=8){
        __syncthreads();
        for (int idx=c; idx<256; idx+=128)
            tj[idx]=tpf[((size_t)i*NTOK+j0)*32 + idx];
        __syncthreads();
        #pragma unroll
        for (int jj=0;jj<8;jj++){
            int j=j0+jj;
            float a=uiv+g_u[(size_t)j*256+128+c];
            const float4* tp=(const float4*)&tj[jj*32];
            #pragma unroll
            for (int k4=0;k4<8;k4++){
                float4 t4=tp[k4];
                a += w[k4].x*t4.x + w[k4].y*t4.y + w[k4].z*t4.z + w[k4].w*t4.w;
            }
            outp[((size_t)i*NTOK+j)*128+c]=a;
        }
    }
}

extern "C" void kernel_launch(void* const* d_in, const int* in_sizes, int n_in,
                              void* d_out, int out_size)
{
    const float* af      = (const float*)d_in[0];
    const float* tpf     = (const float*)d_in[1];
    const float* W_cond  = (const float*)d_in[2];
    const float* W_ph    = (const float*)d_in[3];
    const float* W_pw    = (const float*)d_in[4];
    const float* W_mlp1  = (const float*)d_in[5];
    const float* W_mlp2  = (const float*)d_in[6];
    const float* pb_ln_w = (const float*)d_in[7];
    const float* pb_ln_b = (const float*)d_in[8];
    const float* pb_w    = (const float*)d_in[9];
    const float* sln_w   = (const float*)d_in[10];
    const float* qkv_w   = (const float*)d_in[11];
    const float* q_bias  = (const float*)d_in[12];
    const float* out_w   = (const float*)d_in[13];
    const float* out_b   = (const float*)d_in[14];
    const float* ada_w   = (const float*)d_in[15];
    const float* ta_w    = (const float*)d_in[16];
    const float* tb_w    = (const float*)d_in[17];
    const float* gate_w  = (const float*)d_in[18];
    const float* gate_b  = (const float*)d_in[19];
    const float* W_tok   = (const float*)d_in[20];
    const float* W_trunk = (const float*)d_in[21];
    const float* W_struct= (const float*)d_in[22];
    const float* W_pairin= (const float*)d_in[23];
    const float* W_outer = (const float*)d_in[24];
    const int*   a2t     = (const int*)d_in[28];
    float* out = (float*)d_out;

    PackArgs pa;
    void* p;
    #define SETP(i,sym,srcp,OUTv,Kv,Lv) \
        cudaGetSymbolAddress(&p, sym); \
        pa.d[i] = PackDesc{ srcp, (float*)p, OUTv, Kv, Lv };
    SETP(0,  gP_cond,   W_cond,   128,128,1);
    SETP(1,  gP_ph,     W_ph,      16,128,1);
    SETP(2,  gP_pw,     W_pw,      16,128,1);
    SETP(3,  gP_sln,    sln_w,    256,128,3);
    SETP(4,  gP_qkv,    qkv_w,    384,128,3);
    SETP(5,  gP_out,    out_w,    128,128,3);
    SETP(6,  gP_ada,    ada_w,    256,128,3);
    SETP(7,  gP_ta,     ta_w,     512,128,3);
    SETP(8,  gP_tb,     tb_w,     128,256,3);
    SETP(9,  gP_gate,   gate_w,   128,128,3);
    SETP(10, gP_tok,    W_tok,    384,128,1);
    SETP(11, gP_trunk,  W_trunk,  384,384,1);
    SETP(12, gP_struc,  W_struct, 384,384,1);
    SETP(13, gP_pairin, W_pairin, 128, 32,1);
    SETP(14, gP_outer,  W_outer,  256,384,1);
    #undef SETP
    k_pack<<<dim3(96,15),256>>>(pa);

    const int NBLK = NATOMS/MB;              // 736
    k_cond<<<NBLK,128>>>(af);
    k_ph  <<<NATOMS/16,256>>>();
    k_pw  <<<NB*128/16,256>>>();
    k_pb  <<<NB*32,128>>>(W_mlp1,W_mlp2,pb_ln_w,pb_ln_b,pb_w);

    const int ATTN_SMEM = (4224+1152+4224+4608)*4;  // 56832 B
    cudaFuncSetAttribute(k_attn, cudaFuncAttributeMaxDynamicSharedMemorySize, ATTN_SMEM);
    for (int l=0;l<NL;l++){
        k_stageA<<<NBLK,128>>>(q_bias,l);
        k_attn  <<<NB*4,128,ATTN_SMEM>>>();
        k_stageC<<<NBLK,128>>>(out_b,gate_b,l);
    }

    k_tokproj<<<NBLK,128>>>();
    k_tokmean<<<NTOK,128>>>(a2t);
    k_trunkstruct<<<NTOK/MB,128>>>(out);
    k_pair<<<NTOK,128>>>(tpf, out + (size_t)2*NTOK*384);
}